// round 10
// baseline (speedup 1.0000x reference)
#include <cuda_runtime.h>
#include <cuda_fp16.h>
#include <cstdint>

// ============================================================================
// LSTMCell on GB300 via mma.sync FP16 (tcgen05 PTX-gated off at target sm_103).
//   gates = [X|H][8192,2048] @ W'[2048,4096] + b -> LSTM elementwise (fused)
// Mainloop accumulates in FP16 (m16n8k16.f16 acc, expected 2x rate of f32-acc)
// over K=128 chunks, then promotes into fp32 master accumulators VIA THE
// TENSOR CORE: accf = chunk_f16 * Identity + accf (f32-acc MMA, no cvt ops).
// C-fragment layout == A-fragment layout (k<8), so the chunk regs feed the
// promotion MMA directly; B = constant identity fragment per lane.
// GEMM: 128x128x32 tiles, 256 thr, 2(M)x4(N) warp grid (64x32 warp tile),
// 4-stage cp.async, occ 2. W gate-interleaved for fused LSTM epilogue.
// ============================================================================

static constexpr int DIN  = 1024;
static constexpr int DOUT = 1024;
static constexpr int BT   = 8192;
static constexpr int KD   = 2048;
static constexpr int NG   = 4096;

// Scratch (module-load allocation; allowed)
__device__ __half g_Xf[(size_t)BT * KD];   // A, m16n8k16 fragment-ordered
__device__ __half g_Wf[(size_t)NG * KD];   // B, fragment-ordered, gate-interleaved

// ---------------------------------------------------------------------------
// conv_x: X = [x|h] -> g_Xf in A-fragment order (fp16).
// uint4 index o = (mt*128 + kt)*32 + lane; lane holds A frag of 16x16 tile.
// ---------------------------------------------------------------------------
__global__ void conv_x(const float* __restrict__ x, const float* __restrict__ h) {
    unsigned o = blockIdx.x * blockDim.x + threadIdx.x;  // 2M uint4
    unsigned lane = o & 31u, kt = (o >> 5) & 127u, mt = o >> 12;
    int r = lane >> 2, c = lane & 3;
    int m0 = mt * 16 + r;
    int kb = kt * 16;
    const float* p = (kb < DIN) ? (x + (size_t)m0 * DIN + kb + 2 * c)
                                : (h + (size_t)m0 * DOUT + (kb - DIN) + 2 * c);
    float2 v00 = *(const float2*)p;
    float2 v01 = *(const float2*)(p + 8);
    const float* q = p + 8 * 1024;  // DIN == DOUT == 1024
    float2 v10 = *(const float2*)q;
    float2 v11 = *(const float2*)(q + 8);
    __half2 h0 = __float22half2_rn(v00);
    __half2 h1 = __float22half2_rn(v10);
    __half2 h2 = __float22half2_rn(v01);
    __half2 h3 = __float22half2_rn(v11);
    uint4 rr;
    rr.x = *(unsigned*)&h0; rr.y = *(unsigned*)&h1;
    rr.z = *(unsigned*)&h2; rr.w = *(unsigned*)&h3;
    ((uint4*)g_Xf)[o] = rr;
}

// ---------------------------------------------------------------------------
// conv_w: W[k,1024] per gate -> g_Wf B-fragment order, gate-interleaved.
// uint4 index = (nt*64 + ktp)*32 + lane  (ktp = k/32 chunk, two k16 steps)
// ---------------------------------------------------------------------------
__global__ void conv_w(const float* __restrict__ WI, const float* __restrict__ WF,
                       const float* __restrict__ WG, const float* __restrict__ WO) {
    __shared__ float sT[32][33];  // [k_local][n_local]
    int tx = threadIdx.x, ty = threadIdx.y;  // 32 x 8
    int bx = blockIdx.x;                     // 0..127
    int gate = bx >> 5;
    int n0 = (bx & 31) * 32;                 // within gate
    int k0 = blockIdx.y * 32;                // ktp = k0/32
    const float* W = (gate == 0) ? WI : (gate == 1) ? WF : (gate == 2) ? WG : WO;
#pragma unroll
    for (int i = 0; i < 4; i++)
        sT[ty + 8 * i][tx] = W[(size_t)(k0 + ty + 8 * i) * DOUT + n0 + tx];
    __syncthreads();
    int t = ty * 32 + tx;
    if (t < 128) {
        int n_l = t >> 2, c = t & 3;
        int n_ing = n0 + n_l;
        int np = n_ing * 4 + gate;           // interleaved global col
        int nt = np >> 3;
        int lane = (np & 7) * 4 + c;
        __half2 p0 = __floats2half2_rn(sT[2*c][n_l],      sT[2*c+1][n_l]);
        __half2 p1 = __floats2half2_rn(sT[2*c+8][n_l],    sT[2*c+9][n_l]);
        __half2 p2 = __floats2half2_rn(sT[16+2*c][n_l],   sT[16+2*c+1][n_l]);
        __half2 p3 = __floats2half2_rn(sT[16+2*c+8][n_l], sT[16+2*c+9][n_l]);
        uint4 rr;
        rr.x = *(unsigned*)&p0; rr.y = *(unsigned*)&p1;
        rr.z = *(unsigned*)&p2; rr.w = *(unsigned*)&p3;
        ((uint4*)g_Wf)[((size_t)nt * 64 + (k0 >> 5)) * 32 + lane] = rr;
    }
}

// ---------------------------------------------------------------------------
// Fused GEMM + LSTM: 128x128x32 tiles, 256 threads, 4-stage cp.async, occ 2.
// Warp grid 2(M) x 4(N); warp tile 64x32 (4 m-tiles x 4 n-tiles), m16n8k16.
// FP16 accumulate over K=128 chunks; tensor-core promotion to fp32.
// ---------------------------------------------------------------------------
static constexpr int ITERS = KD / 32;        // 64
static constexpr int ESTRIDE = 132;
static constexpr int SMEM_TOTAL = 128 * ESTRIDE * 4;  // 67584 >= 4*16KB pipeline

__device__ __forceinline__ void cpa16(unsigned saddr, const void* g) {
    size_t gp = __cvta_generic_to_global(g);
    asm volatile("cp.async.cg.shared.global [%0], [%1], 16;" :: "r"(saddr), "l"(gp) : "memory");
}

// fp32-accumulate mma (also used for the promotion step)
__device__ __forceinline__ void mma_f32acc(float* d, uint4 a, unsigned b0, unsigned b1) {
    asm volatile(
        "mma.sync.aligned.m16n8k16.row.col.f32.f16.f16.f32 "
        "{%0,%1,%2,%3}, {%4,%5,%6,%7}, {%8,%9}, {%0,%1,%2,%3};"
        : "+f"(d[0]), "+f"(d[1]), "+f"(d[2]), "+f"(d[3])
        : "r"(a.x), "r"(a.y), "r"(a.z), "r"(a.w), "r"(b0), "r"(b1));
}

// fp16-accumulate mma (mainloop workhorse)
__device__ __forceinline__ void mma_f16acc(unsigned* c, uint4 a, unsigned b0, unsigned b1) {
    asm volatile(
        "mma.sync.aligned.m16n8k16.row.col.f16.f16.f16.f16 "
        "{%0,%1}, {%2,%3,%4,%5}, {%6,%7}, {%0,%1};"
        : "+r"(c[0]), "+r"(c[1])
        : "r"(a.x), "r"(a.y), "r"(a.z), "r"(a.w), "r"(b0), "r"(b1));
}

__device__ __forceinline__ float sigm(float x) { return 1.f / (1.f + __expf(-x)); }
__device__ __forceinline__ float tanhx(float x) { return 2.f / (1.f + __expf(-2.f * x)) - 1.f; }

__global__ void __launch_bounds__(256, 2)
gemm_lstm(const float* __restrict__ cin,
          const float* __restrict__ bI, const float* __restrict__ bF,
          const float* __restrict__ bG, const float* __restrict__ bO,
          float* __restrict__ out) {
    extern __shared__ float smem[];
    __shared__ float sbias[128];
    unsigned sbase = (unsigned)__cvta_generic_to_shared(smem);
    int tid = threadIdx.x;
    int bx = blockIdx.x;  // n' block 0..31
    int by = blockIdx.y;  // m block 0..63
    int mt0 = by * 8, nt0 = bx * 16;
    int warp = tid >> 5, lane = tid & 31;
    int wm = warp & 1, wn = warp >> 1;   // 2 m-warps x 4 n-warps

    if (tid < 128) {
        int gate = tid & 3, n_ing = bx * 32 + (tid >> 2);
        const float* src = (gate == 0) ? bI : (gate == 1) ? bF : (gate == 2) ? bG : bO;
        sbias[tid] = src[n_ing];
    }

    // Identity B-fragment for the promotion MMA: B[k][n] = delta(k,n), k<8.
    // Per lane (g = lane>>2, c = lane&3): b0 = {delta(2c,g), delta(2c+1,g)} fp16.
    int g_ = lane >> 2, c_ = lane & 3;
    unsigned ident = (g_ == 2 * c_) ? 0x3C00u : ((g_ == 2 * c_ + 1) ? 0x3C000000u : 0u);

    float acc[4][4][4];      // fp32 master accumulators
    unsigned c16[4][4][2];   // fp16 chunk accumulators (fp16x2 pairs)
#pragma unroll
    for (int mi = 0; mi < 4; ++mi)
#pragma unroll
        for (int ni = 0; ni < 4; ++ni) {
#pragma unroll
            for (int e = 0; e < 4; ++e) acc[mi][ni][e] = 0.f;
            c16[mi][ni][0] = 0u; c16[mi][ni][1] = 0u;
        }

    const uint4* Xf4 = (const uint4*)g_Xf;
    const uint4* Wf4 = (const uint4*)g_Wf;

    auto load_stage = [&](int it, int s) {
        unsigned st = sbase + (unsigned)s * 16384u;
#pragma unroll
        for (int i = 0; i < 2; ++i) {  // A: 512 uint4 (8 mt x 2 ktl x 32 lanes)
            int u = tid + i * 256;
            int mtl = u >> 6, rest = u & 63;  // rest = ktl*32 + lane
            cpa16(st + (unsigned)u * 16u,
                  Xf4 + ((size_t)(mt0 + mtl) * 128 + it * 2) * 32 + rest);
        }
#pragma unroll
        for (int i = 0; i < 2; ++i) {  // B: 512 uint4 (16 nt x 32 lanes)
            int u = tid + i * 256;
            int ntl = u >> 5, ln = u & 31;
            cpa16(st + 8192u + (unsigned)u * 16u,
                  Wf4 + ((size_t)(nt0 + ntl) * 64 + it) * 32 + ln);
        }
    };

    load_stage(0, 0);
    asm volatile("cp.async.commit_group;" ::: "memory");
    load_stage(1, 1);
    asm volatile("cp.async.commit_group;" ::: "memory");
    load_stage(2, 2);
    asm volatile("cp.async.commit_group;" ::: "memory");

    for (int it = 0; it < ITERS; ++it) {
        int s = it & 3;
        if (it + 3 < ITERS) {
            load_stage(it + 3, (it + 3) & 3);
            asm volatile("cp.async.commit_group;" ::: "memory");
            asm volatile("cp.async.wait_group 3;" ::: "memory");
        } else if (it == ITERS - 3) {
            asm volatile("cp.async.wait_group 2;" ::: "memory");
        } else if (it == ITERS - 2) {
            asm volatile("cp.async.wait_group 1;" ::: "memory");
        } else {
            asm volatile("cp.async.wait_group 0;" ::: "memory");
        }
        __syncthreads();

        const uint4* sA = (const uint4*)(smem + s * 4096);
        const uint4* sB = sA + 512;

        uint4 b[4];
#pragma unroll
        for (int ni = 0; ni < 4; ++ni)
            b[ni] = sB[(wn * 4 + ni) * 32 + lane];
#pragma unroll
        for (int kk = 0; kk < 2; ++kk) {
#pragma unroll
            for (int mip = 0; mip < 2; ++mip) {
                uint4 a0 = sA[((wm * 4 + mip * 2 + 0) * 2 + kk) * 32 + lane];
                uint4 a1 = sA[((wm * 4 + mip * 2 + 1) * 2 + kk) * 32 + lane];
#pragma unroll
                for (int ni = 0; ni < 4; ++ni) {
                    unsigned b0 = kk ? b[ni].z : b[ni].x;
                    unsigned b1 = kk ? b[ni].w : b[ni].y;
                    mma_f16acc(c16[mip * 2 + 0][ni], a0, b0, b1);
                    mma_f16acc(c16[mip * 2 + 1][ni], a1, b0, b1);
                }
            }
        }

        // Promote fp16 chunk accumulators into fp32 every 4 iterations (K=128)
        // via tensor core: acc = chunk * Identity + acc. No cvt instructions.
        if ((it & 3) == 3) {
#pragma unroll
            for (int mi = 0; mi < 4; ++mi)
#pragma unroll
                for (int ni = 0; ni < 4; ++ni) {
                    uint4 ap = make_uint4(c16[mi][ni][0], c16[mi][ni][1], 0u, 0u);
                    mma_f32acc(acc[mi][ni], ap, ident, 0u);
                    c16[mi][ni][0] = 0u; c16[mi][ni][1] = 0u;
                }
        }
        __syncthreads();
    }

    // -------- Fused epilogue: stage accs to smem, then LSTM --------
#pragma unroll
    for (int mi = 0; mi < 4; ++mi) {
#pragma unroll
        for (int ni = 0; ni < 4; ++ni) {
            int r0 = wm * 64 + mi * 16 + (lane >> 2);
            int nn = wn * 32 + ni * 8 + (lane & 3) * 2;
            *(float2*)&smem[r0 * ESTRIDE + nn] = make_float2(acc[mi][ni][0], acc[mi][ni][1]);
            *(float2*)&smem[(r0 + 8) * ESTRIDE + nn] = make_float2(acc[mi][ni][2], acc[mi][ni][3]);
        }
    }
    __syncthreads();

    float4 b4 = *(const float4*)&sbias[lane * 4];
    int n_ing = bx * 32 + lane;
#pragma unroll 4
    for (int pass = 0; pass < 16; ++pass) {
        int r = pass * 8 + warp;
        float4 g4 = *(const float4*)&smem[r * ESTRIDE + lane * 4];
        int m = by * 128 + r;
        float cval = __ldg(&cin[(size_t)m * DOUT + n_ing]);
        float I = sigm(g4.x + b4.x);
        float F = sigm(g4.y + b4.y);
        float G = tanhx(g4.z + b4.z);
        float O = sigm(g4.w + b4.w);
        float C = F * cval + I * G;
        out[(size_t)m * DOUT + n_ing] = O * tanhx(C);
        out[(size_t)BT * DOUT + (size_t)m * DOUT + n_ing] = C;
    }
}

// ---------------------------------------------------------------------------
// Launch
// ---------------------------------------------------------------------------
extern "C" void kernel_launch(void* const* d_in, const int* in_sizes, int n_in,
                              void* d_out, int out_size) {
    const float* x  = (const float*)d_in[0];
    const float* h  = (const float*)d_in[1];
    const float* c  = (const float*)d_in[2];
    const float* WI = (const float*)d_in[3];
    const float* bI = (const float*)d_in[4];
    const float* WF = (const float*)d_in[5];
    const float* bF = (const float*)d_in[6];
    const float* WG = (const float*)d_in[7];
    const float* bG = (const float*)d_in[8];
    const float* WO = (const float*)d_in[9];
    const float* bO = (const float*)d_in[10];
    float* out = (float*)d_out;

    conv_x<<<(BT / 16) * (KD / 16) * 32 / 256, 256>>>(x, h);
    conv_w<<<dim3(128, 64), dim3(32, 8)>>>(WI, WF, WG, WO);

    cudaFuncSetAttribute(gemm_lstm, cudaFuncAttributeMaxDynamicSharedMemorySize, SMEM_TOTAL);
    gemm_lstm<<<dim3(32, 64), 256, SMEM_TOTAL>>>(c, bI, bF, bG, bO, out);
}

// round 13
// speedup vs baseline: 1.0757x; 1.0757x over previous
#include <cuda_runtime.h>
#include <cuda_fp16.h>
#include <cstdint>

// ============================================================================
// LSTMCell on GB300 via mma.sync FP16 (tcgen05 PTX-gated off at target sm_103).
//   gates = [X|H][8192,2048] @ W'[2048,4096] + b -> LSTM elementwise (fused)
// fp16 m16n8k16, fp32 accumulate (11-bit significand == tf32 precision).
// GEMM: 256x128x32 CTA tile, 512 thr, 4(M)x4(N) warp grid, 64x32 warp tile,
// 4-stage cp.async, occ 1 (4 warps/SMSP). 256-row tile halves B smem re-reads:
// crossbar 937 cyc/iter < HMMA 1024 cyc/iter -> tensor-issue-bound w/ slack.
// W gate-interleaved (n' = n_in_gate*4 + gate); fused LSTM epilogue in 2 halves.
// ============================================================================

static constexpr int DIN  = 1024;
static constexpr int DOUT = 1024;
static constexpr int BT   = 8192;
static constexpr int KD   = 2048;
static constexpr int NG   = 4096;

// Scratch (module-load allocation; allowed)
__device__ __half g_Xf[(size_t)BT * KD];   // A, m16n8k16 fragment-ordered
__device__ __half g_Wf[(size_t)NG * KD];   // B, fragment-ordered, gate-interleaved

// ---------------------------------------------------------------------------
// conv_x: X = [x|h] -> g_Xf in A-fragment order (fp16).
// uint4 index o = (mt*128 + kt)*32 + lane; lane holds A frag of 16x16 tile.
// ---------------------------------------------------------------------------
__global__ void conv_x(const float* __restrict__ x, const float* __restrict__ h) {
    unsigned o = blockIdx.x * blockDim.x + threadIdx.x;  // 2M uint4
    unsigned lane = o & 31u, kt = (o >> 5) & 127u, mt = o >> 12;
    int r = lane >> 2, c = lane & 3;
    int m0 = mt * 16 + r;
    int kb = kt * 16;
    const float* p = (kb < DIN) ? (x + (size_t)m0 * DIN + kb + 2 * c)
                                : (h + (size_t)m0 * DOUT + (kb - DIN) + 2 * c);
    float2 v00 = *(const float2*)p;
    float2 v01 = *(const float2*)(p + 8);
    const float* q = p + 8 * 1024;  // DIN == DOUT == 1024
    float2 v10 = *(const float2*)q;
    float2 v11 = *(const float2*)(q + 8);
    __half2 h0 = __float22half2_rn(v00);
    __half2 h1 = __float22half2_rn(v10);
    __half2 h2 = __float22half2_rn(v01);
    __half2 h3 = __float22half2_rn(v11);
    uint4 rr;
    rr.x = *(unsigned*)&h0; rr.y = *(unsigned*)&h1;
    rr.z = *(unsigned*)&h2; rr.w = *(unsigned*)&h3;
    ((uint4*)g_Xf)[o] = rr;
}

// ---------------------------------------------------------------------------
// conv_w: W[k,1024] per gate -> g_Wf B-fragment order, gate-interleaved.
// uint4 index = (nt*64 + ktp)*32 + lane  (ktp = k/32 chunk, two k16 steps)
// ---------------------------------------------------------------------------
__global__ void conv_w(const float* __restrict__ WI, const float* __restrict__ WF,
                       const float* __restrict__ WG, const float* __restrict__ WO) {
    __shared__ float sT[32][33];  // [k_local][n_local]
    int tx = threadIdx.x, ty = threadIdx.y;  // 32 x 8
    int bx = blockIdx.x;                     // 0..127
    int gate = bx >> 5;
    int n0 = (bx & 31) * 32;                 // within gate
    int k0 = blockIdx.y * 32;                // ktp = k0/32
    const float* W = (gate == 0) ? WI : (gate == 1) ? WF : (gate == 2) ? WG : WO;
#pragma unroll
    for (int i = 0; i < 4; i++)
        sT[ty + 8 * i][tx] = W[(size_t)(k0 + ty + 8 * i) * DOUT + n0 + tx];
    __syncthreads();
    int t = ty * 32 + tx;
    if (t < 128) {
        int n_l = t >> 2, c = t & 3;
        int n_ing = n0 + n_l;
        int np = n_ing * 4 + gate;           // interleaved global col
        int nt = np >> 3;
        int lane = (np & 7) * 4 + c;
        __half2 p0 = __floats2half2_rn(sT[2*c][n_l],      sT[2*c+1][n_l]);
        __half2 p1 = __floats2half2_rn(sT[2*c+8][n_l],    sT[2*c+9][n_l]);
        __half2 p2 = __floats2half2_rn(sT[16+2*c][n_l],   sT[16+2*c+1][n_l]);
        __half2 p3 = __floats2half2_rn(sT[16+2*c+8][n_l], sT[16+2*c+9][n_l]);
        uint4 rr;
        rr.x = *(unsigned*)&p0; rr.y = *(unsigned*)&p1;
        rr.z = *(unsigned*)&p2; rr.w = *(unsigned*)&p3;
        ((uint4*)g_Wf)[((size_t)nt * 64 + (k0 >> 5)) * 32 + lane] = rr;
    }
}

// ---------------------------------------------------------------------------
// Fused GEMM + LSTM: 256x128x32 tiles, 512 threads, 4-stage cp.async, occ 1.
// Warp grid 4(M) x 4(N); warp tile 64x32 (4 m-tiles x 4 n-tiles), m16n8k16.
// Stage = 24KB: A 1024 uint4 (16mt x 2ktl x 32 lane) + B 512 uint4
// (16nt x 32 lane). One __syncthreads per iteration (cutlass order).
// ---------------------------------------------------------------------------
static constexpr int ITERS = KD / 32;         // 64
static constexpr int ESTRIDE = 132;
static constexpr int SMEM_TOTAL = 4 * 24576;  // 98304 (epilogue needs 67.6KB)

__device__ __forceinline__ void cpa16(unsigned saddr, const void* g) {
    size_t gp = __cvta_generic_to_global(g);
    asm volatile("cp.async.cg.shared.global [%0], [%1], 16;" :: "r"(saddr), "l"(gp) : "memory");
}

__device__ __forceinline__ void mma_f16(float* d, uint4 a, unsigned b0, unsigned b1) {
    asm volatile(
        "mma.sync.aligned.m16n8k16.row.col.f32.f16.f16.f32 "
        "{%0,%1,%2,%3}, {%4,%5,%6,%7}, {%8,%9}, {%0,%1,%2,%3};"
        : "+f"(d[0]), "+f"(d[1]), "+f"(d[2]), "+f"(d[3])
        : "r"(a.x), "r"(a.y), "r"(a.z), "r"(a.w), "r"(b0), "r"(b1));
}

__device__ __forceinline__ float sigm(float x) { return 1.f / (1.f + __expf(-x)); }
__device__ __forceinline__ float tanhx(float x) { return 2.f / (1.f + __expf(-2.f * x)) - 1.f; }

__global__ void __launch_bounds__(512, 1)
gemm_lstm(const float* __restrict__ cin,
          const float* __restrict__ bI, const float* __restrict__ bF,
          const float* __restrict__ bG, const float* __restrict__ bO,
          float* __restrict__ out) {
    extern __shared__ float smem[];
    __shared__ float sbias[128];
    unsigned sbase = (unsigned)__cvta_generic_to_shared(smem);
    int tid = threadIdx.x;
    int bx = blockIdx.x;  // n' block 0..31 (16 n-tiles = 128 interleaved cols)
    int by = blockIdx.y;  // m block 0..31 (256 rows)
    int mt0 = by * 16, nt0 = bx * 16;
    int warp = tid >> 5, lane = tid & 31;
    int wm = warp & 3, wn = warp >> 2;  // 4 m-warps x 4 n-warps

    if (tid < 128) {
        int gate = tid & 3, n_ing = bx * 32 + (tid >> 2);
        const float* src = (gate == 0) ? bI : (gate == 1) ? bF : (gate == 2) ? bG : bO;
        sbias[tid] = src[n_ing];
    }

    float acc[4][4][4];
#pragma unroll
    for (int mi = 0; mi < 4; ++mi)
#pragma unroll
        for (int ni = 0; ni < 4; ++ni)
#pragma unroll
            for (int e = 0; e < 4; ++e) acc[mi][ni][e] = 0.f;

    const uint4* Xf4 = (const uint4*)g_Xf;
    const uint4* Wf4 = (const uint4*)g_Wf;

    auto load_stage = [&](int it, int s) {
        unsigned st = sbase + (unsigned)s * 24576u;
#pragma unroll
        for (int i = 0; i < 2; ++i) {  // A: 1024 uint4 (16 mt x 2 ktl x 32 lanes)
            int u = tid + i * 512;
            int mtl = u >> 6, rest = u & 63;  // rest = ktl*32 + lane
            cpa16(st + (unsigned)u * 16u,
                  Xf4 + ((size_t)(mt0 + mtl) * 128 + it * 2) * 32 + rest);
        }
        // B: 512 uint4 (16 nt x 32 lanes)
        cpa16(st + 16384u + (unsigned)tid * 16u,
              Wf4 + ((size_t)(nt0 + (tid >> 5)) * 64 + it) * 32 + (tid & 31));
    };

    // Prologue: 3 stages in flight
    load_stage(0, 0);
    asm volatile("cp.async.commit_group;" ::: "memory");
    load_stage(1, 1);
    asm volatile("cp.async.commit_group;" ::: "memory");
    load_stage(2, 2);
    asm volatile("cp.async.commit_group;" ::: "memory");

    for (int it = 0; it < ITERS; ++it) {
        int s = it & 3;
        if (it < ITERS - 3) {
            asm volatile("cp.async.wait_group 2;" ::: "memory");
        } else if (it == ITERS - 3) {
            asm volatile("cp.async.wait_group 2;" ::: "memory");
        } else if (it == ITERS - 2) {
            asm volatile("cp.async.wait_group 1;" ::: "memory");
        } else {
            asm volatile("cp.async.wait_group 0;" ::: "memory");
        }
        __syncthreads();  // publishes stage s; protects stage (it+3)&3 = (it-1)&3

        if (it + 3 < ITERS) {
            load_stage(it + 3, (it + 3) & 3);
            asm volatile("cp.async.commit_group;" ::: "memory");
        }

        const uint4* sA = (const uint4*)(smem + s * 6144);
        const uint4* sB = sA + 1024;

        uint4 b[4];
#pragma unroll
        for (int ni = 0; ni < 4; ++ni)
            b[ni] = sB[(wn * 4 + ni) * 32 + lane];
#pragma unroll
        for (int kk = 0; kk < 2; ++kk) {
            uint4 a[4];
#pragma unroll
            for (int mi = 0; mi < 4; ++mi)
                a[mi] = sA[((wm * 4 + mi) * 2 + kk) * 32 + lane];
#pragma unroll
            for (int ni = 0; ni < 4; ++ni) {
                unsigned b0 = kk ? b[ni].z : b[ni].x;
                unsigned b1 = kk ? b[ni].w : b[ni].y;
#pragma unroll
                for (int mi = 0; mi < 4; ++mi)
                    mma_f16(acc[mi][ni], a[mi], b0, b1);
            }
        }
    }

    // -------- Fused epilogue: two 128-row halves through smem --------
    float4 b4 = *(const float4*)&sbias[lane * 4];
    int n_ing = bx * 32 + lane;
#pragma unroll
    for (int half = 0; half < 2; ++half) {
        __syncthreads();  // mainloop reads / previous-half reads complete
        if ((wm >> 1) == half) {
            int wml = wm & 1;
#pragma unroll
            for (int mi = 0; mi < 4; ++mi) {
#pragma unroll
                for (int ni = 0; ni < 4; ++ni) {
                    int r0 = wml * 64 + mi * 16 + (lane >> 2);
                    int nn = wn * 32 + ni * 8 + (lane & 3) * 2;
                    *(float2*)&smem[r0 * ESTRIDE + nn] =
                        make_float2(acc[mi][ni][0], acc[mi][ni][1]);
                    *(float2*)&smem[(r0 + 8) * ESTRIDE + nn] =
                        make_float2(acc[mi][ni][2], acc[mi][ni][3]);
                }
            }
        }
        __syncthreads();
#pragma unroll 4
        for (int rr = 0; rr < 8; ++rr) {
            int r = rr * 16 + warp;
            float4 g4 = *(const float4*)&smem[r * ESTRIDE + lane * 4];
            int m = by * 256 + half * 128 + r;
            float cval = __ldg(&cin[(size_t)m * DOUT + n_ing]);
            float I = sigm(g4.x + b4.x);
            float F = sigm(g4.y + b4.y);
            float G = tanhx(g4.z + b4.z);
            float O = sigm(g4.w + b4.w);
            float C = F * cval + I * G;
            out[(size_t)m * DOUT + n_ing] = O * tanhx(C);
            out[(size_t)BT * DOUT + (size_t)m * DOUT + n_ing] = C;
        }
    }
}

// ---------------------------------------------------------------------------
// Launch
// ---------------------------------------------------------------------------
extern "C" void kernel_launch(void* const* d_in, const int* in_sizes, int n_in,
                              void* d_out, int out_size) {
    const float* x  = (const float*)d_in[0];
    const float* h  = (const float*)d_in[1];
    const float* c  = (const float*)d_in[2];
    const float* WI = (const float*)d_in[3];
    const float* bI = (const float*)d_in[4];
    const float* WF = (const float*)d_in[5];
    const float* bF = (const float*)d_in[6];
    const float* WG = (const float*)d_in[7];
    const float* bG = (const float*)d_in[8];
    const float* WO = (const float*)d_in[9];
    const float* bO = (const float*)d_in[10];
    float* out = (float*)d_out;

    conv_x<<<(BT / 16) * (KD / 16) * 32 / 256, 256>>>(x, h);
    conv_w<<<dim3(128, 64), dim3(32, 8)>>>(WI, WF, WG, WO);

    cudaFuncSetAttribute(gemm_lstm, cudaFuncAttributeMaxDynamicSharedMemorySize, SMEM_TOTAL);
    gemm_lstm<<<dim3(32, 32), 512, SMEM_TOTAL>>>(c, bI, bF, bG, bO, out);
}

// round 15
// speedup vs baseline: 1.3417x; 1.2473x over previous
#include <cuda_runtime.h>
#include <cuda_fp16.h>
#include <cstdint>

// ============================================================================
// LSTMCell on GB300 via mma.sync FP16 (tcgen05 PTX-gated off at target sm_103).
//   gates = [X|H][8192,2048] @ W'[2048,4096] + b -> LSTM elementwise (fused)
// fp16 m16n8k16, fp32 accumulate (11-bit significand == tf32 precision).
// GEMM: champion config — 128x128x32 CTA tile, 256 thr, 4(M)x2(N) warp grid,
// 32x64 warp tile, 4-stage cp.async, occ 2. (Every probed deviation — occ 1,
// fat warp tiles, fewer syncs, fp16-acc, 256-row tiles — measured slower.)
// Converters MERGED into one launch: conv_x blocks + conv_w blocks overlap.
// W gate-interleaved (n' = n_in_gate*4 + gate) for in-kernel LSTM epilogue.
// ============================================================================

static constexpr int DIN  = 1024;
static constexpr int DOUT = 1024;
static constexpr int BT   = 8192;
static constexpr int KD   = 2048;
static constexpr int NG   = 4096;

// Scratch (module-load allocation; allowed)
__device__ __half g_Xf[(size_t)BT * KD];   // A, m16n8k16 fragment-ordered
__device__ __half g_Wf[(size_t)NG * KD];   // B, fragment-ordered, gate-interleaved

// ---------------------------------------------------------------------------
// Merged converter: blocks [0, 8192) do X; blocks [8192, 16384) do W.
// conv_x part: X = [x|h] -> g_Xf in A-fragment order (fp16).
//   uint4 index o = (mt*128 + kt)*32 + lane; lane holds A frag of 16x16 tile.
// conv_w part: W[k,1024] per gate -> g_Wf B-fragment order, gate-interleaved.
//   uint4 index = (nt*64 + ktp)*32 + lane (ktp = k/32 chunk, two k16 steps).
// ---------------------------------------------------------------------------
__global__ void conv_all(const float* __restrict__ x, const float* __restrict__ h,
                         const float* __restrict__ WI, const float* __restrict__ WF,
                         const float* __restrict__ WG, const float* __restrict__ WO) {
    if (blockIdx.x < 8192) {
        // ---- X converter ----
        unsigned o = blockIdx.x * 256 + threadIdx.x;  // 2M uint4
        unsigned lane = o & 31u, kt = (o >> 5) & 127u, mt = o >> 12;
        int r = lane >> 2, c = lane & 3;
        int m0 = mt * 16 + r;
        int kb = kt * 16;
        const float* p = (kb < DIN) ? (x + (size_t)m0 * DIN + kb + 2 * c)
                                    : (h + (size_t)m0 * DOUT + (kb - DIN) + 2 * c);
        float2 v00 = *(const float2*)p;
        float2 v01 = *(const float2*)(p + 8);
        const float* q = p + 8 * 1024;  // DIN == DOUT == 1024
        float2 v10 = *(const float2*)q;
        float2 v11 = *(const float2*)(q + 8);
        __half2 h0 = __float22half2_rn(v00);
        __half2 h1 = __float22half2_rn(v10);
        __half2 h2 = __float22half2_rn(v01);
        __half2 h3 = __float22half2_rn(v11);
        uint4 rr;
        rr.x = *(unsigned*)&h0; rr.y = *(unsigned*)&h1;
        rr.z = *(unsigned*)&h2; rr.w = *(unsigned*)&h3;
        ((uint4*)g_Xf)[o] = rr;
    } else {
        // ---- W converter ----
        __shared__ float sT[32][33];  // [k_local][n_local]
        int bid = blockIdx.x - 8192;
        int bx = bid & 127;           // 0..127  (gate*32 + n-block)
        int by = bid >> 7;            // 0..63   (k-block)
        int t = threadIdx.x;
        int tx = t & 31, ty = t >> 5; // 32 x 8
        int gate = bx >> 5;
        int n0 = (bx & 31) * 32;      // within gate
        int k0 = by * 32;             // ktp = k0/32
        const float* W = (gate == 0) ? WI : (gate == 1) ? WF : (gate == 2) ? WG : WO;
#pragma unroll
        for (int i = 0; i < 4; i++)
            sT[ty + 8 * i][tx] = W[(size_t)(k0 + ty + 8 * i) * DOUT + n0 + tx];
        __syncthreads();
        if (t < 128) {
            int n_l = t >> 2, c = t & 3;
            int n_ing = n0 + n_l;
            int np = n_ing * 4 + gate;    // interleaved global col
            int nt = np >> 3;
            int lane = (np & 7) * 4 + c;
            __half2 p0 = __floats2half2_rn(sT[2*c][n_l],      sT[2*c+1][n_l]);
            __half2 p1 = __floats2half2_rn(sT[2*c+8][n_l],    sT[2*c+9][n_l]);
            __half2 p2 = __floats2half2_rn(sT[16+2*c][n_l],   sT[16+2*c+1][n_l]);
            __half2 p3 = __floats2half2_rn(sT[16+2*c+8][n_l], sT[16+2*c+9][n_l]);
            uint4 rr;
            rr.x = *(unsigned*)&p0; rr.y = *(unsigned*)&p1;
            rr.z = *(unsigned*)&p2; rr.w = *(unsigned*)&p3;
            ((uint4*)g_Wf)[((size_t)nt * 64 + (k0 >> 5)) * 32 + lane] = rr;
        }
    }
}

// ---------------------------------------------------------------------------
// Fused GEMM + LSTM: 128x128x32 tiles, 256 threads, 4-stage cp.async, occ 2.
// Warp grid 4(M) x 2(N); warp tile 32x64 (2 m-tiles x 8 n-tiles), m16n8k16.
// ---------------------------------------------------------------------------
static constexpr int ITERS = KD / 32;        // 64
static constexpr int ESTRIDE = 132;
static constexpr int SMEM_TOTAL = 128 * ESTRIDE * 4;  // 67584 >= 4*16KB pipeline

__device__ __forceinline__ void cpa16(unsigned saddr, const void* g) {
    size_t gp = __cvta_generic_to_global(g);
    asm volatile("cp.async.cg.shared.global [%0], [%1], 16;" :: "r"(saddr), "l"(gp) : "memory");
}

__device__ __forceinline__ void mma_f16(float* d, uint4 a, unsigned b0, unsigned b1) {
    asm volatile(
        "mma.sync.aligned.m16n8k16.row.col.f32.f16.f16.f32 "
        "{%0,%1,%2,%3}, {%4,%5,%6,%7}, {%8,%9}, {%0,%1,%2,%3};"
        : "+f"(d[0]), "+f"(d[1]), "+f"(d[2]), "+f"(d[3])
        : "r"(a.x), "r"(a.y), "r"(a.z), "r"(a.w), "r"(b0), "r"(b1));
}

__device__ __forceinline__ float sigm(float x) { return 1.f / (1.f + __expf(-x)); }
__device__ __forceinline__ float tanhx(float x) { return 2.f / (1.f + __expf(-2.f * x)) - 1.f; }

__global__ void __launch_bounds__(256, 2)
gemm_lstm(const float* __restrict__ cin,
          const float* __restrict__ bI, const float* __restrict__ bF,
          const float* __restrict__ bG, const float* __restrict__ bO,
          float* __restrict__ out) {
    extern __shared__ float smem[];
    __shared__ float sbias[128];
    unsigned sbase = (unsigned)__cvta_generic_to_shared(smem);
    int tid = threadIdx.x;
    int bx = blockIdx.x;  // n' block 0..31 (16 n-tiles = 128 interleaved cols)
    int by = blockIdx.y;  // m block 0..63
    int mt0 = by * 8, nt0 = bx * 16;
    int warp = tid >> 5, lane = tid & 31;
    int wm = warp & 3, wn = warp >> 2;

    if (tid < 128) {
        int gate = tid & 3, n_ing = bx * 32 + (tid >> 2);
        const float* src = (gate == 0) ? bI : (gate == 1) ? bF : (gate == 2) ? bG : bO;
        sbias[tid] = src[n_ing];
    }

    float acc[2][8][4];
#pragma unroll
    for (int mi = 0; mi < 2; ++mi)
#pragma unroll
        for (int ni = 0; ni < 8; ++ni)
#pragma unroll
            for (int e = 0; e < 4; ++e) acc[mi][ni][e] = 0.f;

    const uint4* Xf4 = (const uint4*)g_Xf;
    const uint4* Wf4 = (const uint4*)g_Wf;

    auto load_stage = [&](int it, int s) {
        unsigned st = sbase + (unsigned)s * 16384u;
#pragma unroll
        for (int i = 0; i < 2; ++i) {  // A: 512 uint4 (8 mt x 2 ktl x 32 lanes)
            int u = tid + i * 256;
            int mtl = u >> 6, rest = u & 63;  // rest = ktl*32 + lane
            cpa16(st + (unsigned)u * 16u,
                  Xf4 + ((size_t)(mt0 + mtl) * 128 + it * 2) * 32 + rest);
        }
#pragma unroll
        for (int i = 0; i < 2; ++i) {  // B: 512 uint4 (16 nt x 32 lanes)
            int u = tid + i * 256;
            int ntl = u >> 5, ln = u & 31;
            cpa16(st + 8192u + (unsigned)u * 16u,
                  Wf4 + ((size_t)(nt0 + ntl) * 64 + it) * 32 + ln);
        }
    };

    load_stage(0, 0);
    asm volatile("cp.async.commit_group;" ::: "memory");
    load_stage(1, 1);
    asm volatile("cp.async.commit_group;" ::: "memory");
    load_stage(2, 2);
    asm volatile("cp.async.commit_group;" ::: "memory");

    for (int it = 0; it < ITERS; ++it) {
        int s = it & 3;
        if (it + 3 < ITERS) {
            load_stage(it + 3, (it + 3) & 3);
            asm volatile("cp.async.commit_group;" ::: "memory");
            asm volatile("cp.async.wait_group 3;" ::: "memory");
        } else if (it == ITERS - 3) {
            asm volatile("cp.async.wait_group 2;" ::: "memory");
        } else if (it == ITERS - 2) {
            asm volatile("cp.async.wait_group 1;" ::: "memory");
        } else {
            asm volatile("cp.async.wait_group 0;" ::: "memory");
        }
        __syncthreads();

        const uint4* sA = (const uint4*)(smem + s * 4096);
        const uint4* sB = sA + 512;

        uint4 b[8];
#pragma unroll
        for (int ni = 0; ni < 8; ++ni)
            b[ni] = sB[(wn * 8 + ni) * 32 + lane];
#pragma unroll
        for (int kk = 0; kk < 2; ++kk) {
            uint4 a0 = sA[((wm * 2 + 0) * 2 + kk) * 32 + lane];
            uint4 a1 = sA[((wm * 2 + 1) * 2 + kk) * 32 + lane];
#pragma unroll
            for (int ni = 0; ni < 8; ++ni) {
                unsigned b0 = kk ? b[ni].z : b[ni].x;
                unsigned b1 = kk ? b[ni].w : b[ni].y;
                mma_f16(acc[0][ni], a0, b0, b1);
                mma_f16(acc[1][ni], a1, b0, b1);
            }
        }
        __syncthreads();
    }

    // -------- Fused epilogue: stage accs to smem, then LSTM --------
#pragma unroll
    for (int mi = 0; mi < 2; ++mi) {
#pragma unroll
        for (int ni = 0; ni < 8; ++ni) {
            int r0 = wm * 32 + mi * 16 + (lane >> 2);
            int nn = wn * 64 + ni * 8 + (lane & 3) * 2;
            *(float2*)&smem[r0 * ESTRIDE + nn] = make_float2(acc[mi][ni][0], acc[mi][ni][1]);
            *(float2*)&smem[(r0 + 8) * ESTRIDE + nn] = make_float2(acc[mi][ni][2], acc[mi][ni][3]);
        }
    }
    __syncthreads();

    float4 b4 = *(const float4*)&sbias[lane * 4];
    int n_ing = bx * 32 + lane;
#pragma unroll 4
    for (int pass = 0; pass < 16; ++pass) {
        int r = pass * 8 + warp;
        float4 g4 = *(const float4*)&smem[r * ESTRIDE + lane * 4];
        int m = by * 128 + r;
        float cval = __ldg(&cin[(size_t)m * DOUT + n_ing]);
        float I = sigm(g4.x + b4.x);
        float F = sigm(g4.y + b4.y);
        float G = tanhx(g4.z + b4.z);
        float O = sigm(g4.w + b4.w);
        float C = F * cval + I * G;
        out[(size_t)m * DOUT + n_ing] = O * tanhx(C);
        out[(size_t)BT * DOUT + (size_t)m * DOUT + n_ing] = C;
    }
}

// ---------------------------------------------------------------------------
// Launch
// ---------------------------------------------------------------------------
extern "C" void kernel_launch(void* const* d_in, const int* in_sizes, int n_in,
                              void* d_out, int out_size) {
    const float* x  = (const float*)d_in[0];
    const float* h  = (const float*)d_in[1];
    const float* c  = (const float*)d_in[2];
    const float* WI = (const float*)d_in[3];
    const float* bI = (const float*)d_in[4];
    const float* WF = (const float*)d_in[5];
    const float* bF = (const float*)d_in[6];
    const float* WG = (const float*)d_in[7];
    const float* bG = (const float*)d_in[8];
    const float* WO = (const float*)d_in[9];
    const float* bO = (const float*)d_in[10];
    float* out = (float*)d_out;

    conv_all<<<16384, 256>>>(x, h, WI, WF, WG, WO);

    cudaFuncSetAttribute(gemm_lstm, cudaFuncAttributeMaxDynamicSharedMemorySize, SMEM_TOTAL);
    gemm_lstm<<<dim3(32, 64), 256, SMEM_TOTAL>>>(c, bI, bF, bG, bO, out);
}